// round 10
// baseline (speedup 1.0000x reference)
#include <cuda_runtime.h>
#include <cuda_bf16.h>

#define S_LEN 2048
#define B_SZ  16
#define H_DIM 1024

// 8 chunk-partial slabs (race-free -> no init kernel) + final energy
__device__ float g_part[8][B_SZ * H_DIM];
__device__ float g_energy[B_SZ * H_DIM];

// ---------------------------------------------------------------------------
// Kernel 1 (R8-proven, best measured): energy partials.
// j split into 8 chunks of 128 floats. Block = 128 thr (4 warps) covers
// (8 h-rows) x (one chunk); warp owns 2 rows x 16 b = 32 accumulators,
// each LDS.128 feeds 8 FFMAs. grid = 1024 blocks.
// ---------------------------------------------------------------------------
__global__ void __launch_bounds__(128)
energy_kernel(const float* __restrict__ lds,
              const float* __restrict__ W)
{
    __shared__ float4 s_st[16 * 32];     // [b][32 float4] for this chunk (8KB)

    const int t    = threadIdx.x;
    const int warp = t >> 5;
    const int lane = t & 31;
    const int rg   = blockIdx.x >> 3;    // 8-row group (0..127)
    const int ch   = blockIdx.x & 7;     // j-chunk (128 floats = 32 float4)
    const int row0 = rg * 8 + warp * 2;

    const float4* st4 = reinterpret_cast<const float4*>(lds);  // [B][256]
    const float4* W4  = reinterpret_cast<const float4*>(W);    // [H][256]

    #pragma unroll
    for (int i = 0; i < 4; ++i) {
        const int v = t + i * 128;       // 0..511
        const int b = v >> 5;
        const int k = v & 31;
        s_st[v] = st4[b * 256 + ch * 32 + k];
    }
    __syncthreads();

    const float4 w0 = W4[(size_t)row0 * 256 + ch * 32 + lane];
    const float4 w1 = W4[(size_t)(row0 + 1) * 256 + ch * 32 + lane];

    float a[32];                          // a[r*16+b]
    #pragma unroll
    for (int b = 0; b < 16; ++b) {
        const float4 s = s_st[b * 32 + lane];
        a[b]      = w0.x * s.x + w0.y * s.y + w0.z * s.z + w0.w * s.w;
        a[16 + b] = w1.x * s.x + w1.y * s.y + w1.z * s.z + w1.w * s.w;
    }

    // Value-halving butterfly: lane l ends holding warp-total of a[l].
    int n = 32;
    #pragma unroll
    for (int s = 16; s >= 1; s >>= 1) {
        const int  half = n >> 1;
        const bool up   = (lane & s) != 0;
        #pragma unroll
        for (int i = 0; i < half; ++i) {
            const float send = up ? a[i] : a[i + half];
            const float keep = up ? a[i + half] : a[i];
            a[i] = keep + __shfl_xor_sync(0xFFFFFFFF, send, s);
        }
        n = half;
    }

    const int r = lane >> 4;
    const int b = lane & 15;
    g_part[ch][(size_t)b * H_DIM + row0 + r] = a[0];
}

// ---------------------------------------------------------------------------
// Kernel 1b: fold 8 partial slabs + bias into final g_energy.
// 4096 float4 outputs; 16 blocks x 256 thr, one float4 each (all L2-hot).
// ---------------------------------------------------------------------------
__global__ void __launch_bounds__(256)
reduce_kernel(const float* __restrict__ bias)
{
    const int v = blockIdx.x * 256 + threadIdx.x;   // float4 index 0..4095
    const int h4 = v & (H_DIM / 4 - 1);             // float4 index within row

    const float4* b4 = reinterpret_cast<const float4*>(bias);
    float4 acc = b4[h4];
    #pragma unroll
    for (int c = 0; c < 8; ++c) {
        const float4 p = reinterpret_cast<const float4*>(g_part[c])[v];
        acc.x += p.x; acc.y += p.y; acc.z += p.z; acc.w += p.w;
    }
    reinterpret_cast<float4*>(g_energy)[v] = acc;
}

// ---------------------------------------------------------------------------
// Kernel 2: scores[s][b] = sum_h enc[s][b][h] * energy[b][h]
// One block per (b, 8-row s-chunk): final energy row (2 float4/thread,
// L1/L2-hot) in registers, reused 8x. Pure 128 MiB DRAM stream otherwise.
// ---------------------------------------------------------------------------
#define VPS 8
__global__ void __launch_bounds__(128, 8)
score_kernel(const float* __restrict__ enc, float* __restrict__ out)
{
    const int b  = blockIdx.x & (B_SZ - 1);
    const int s0 = (blockIdx.x >> 4) * VPS;
    const int t  = threadIdx.x;

    const float4* e4 = reinterpret_cast<const float4*>(enc);
    const float4* g4 = reinterpret_cast<const float4*>(g_energy);

    const float4 g0 = g4[b * (H_DIM / 4) + t];
    const float4 g1 = g4[b * (H_DIM / 4) + 128 + t];

    float acc[VPS];
    #pragma unroll
    for (int i = 0; i < VPS; ++i) {
        const size_t row = ((size_t)(s0 + i) * B_SZ + b) * (H_DIM / 4);
        const float4 a0 = e4[row + t];
        const float4 a1 = e4[row + 128 + t];
        acc[i] = a0.x * g0.x + a0.y * g0.y + a0.z * g0.z + a0.w * g0.w
               + a1.x * g1.x + a1.y * g1.y + a1.z * g1.z + a1.w * g1.w;
    }

    #pragma unroll
    for (int i = 0; i < VPS; ++i)
        #pragma unroll
        for (int off = 16; off > 0; off >>= 1)
            acc[i] += __shfl_xor_sync(0xFFFFFFFF, acc[i], off);

    __shared__ float red[4][VPS];
    const int warp = t >> 5;
    const int lane = t & 31;
    if (lane == 0) {
        #pragma unroll
        for (int i = 0; i < VPS; ++i)
            red[warp][i] = acc[i];
    }
    __syncthreads();
    if (t < VPS)
        out[(size_t)(s0 + t) * B_SZ + b] =
            red[0][t] + red[1][t] + red[2][t] + red[3][t];
}

// ---------------------------------------------------------------------------
// Kernel 3: softmax over S per column b. 16 blocks x 1024 threads,
// 2 values/thread in registers, two block-wide reductions.
// ---------------------------------------------------------------------------
__global__ void __launch_bounds__(1024)
softmax_kernel(float* __restrict__ out)
{
    const int b = blockIdx.x;
    const int t = threadIdx.x;

    float v0 = out[(size_t)t * B_SZ + b];
    float v1 = out[(size_t)(t + 1024) * B_SZ + b];

    __shared__ float sm[32];
    const int warp = t >> 5, lane = t & 31;

    float mx = fmaxf(v0, v1);
    #pragma unroll
    for (int off = 16; off > 0; off >>= 1)
        mx = fmaxf(mx, __shfl_xor_sync(0xFFFFFFFF, mx, off));
    if (lane == 0) sm[warp] = mx;
    __syncthreads();
    if (warp == 0) {
        float m = sm[lane];
        #pragma unroll
        for (int off = 16; off > 0; off >>= 1)
            m = fmaxf(m, __shfl_xor_sync(0xFFFFFFFF, m, off));
        if (lane == 0) sm[0] = m;
    }
    __syncthreads();
    mx = sm[0];
    __syncthreads();

    v0 = __expf(v0 - mx);
    v1 = __expf(v1 - mx);
    float sum = v0 + v1;
    #pragma unroll
    for (int off = 16; off > 0; off >>= 1)
        sum += __shfl_xor_sync(0xFFFFFFFF, sum, off);
    if (lane == 0) sm[warp] = sum;
    __syncthreads();
    if (warp == 0) {
        float s = sm[lane];
        #pragma unroll
        for (int off = 16; off > 0; off >>= 1)
            s += __shfl_xor_sync(0xFFFFFFFF, s, off);
        if (lane == 0) sm[0] = s;
    }
    __syncthreads();
    const float inv = 1.0f / sm[0];

    out[(size_t)t * B_SZ + b]          = v0 * inv;
    out[(size_t)(t + 1024) * B_SZ + b] = v1 * inv;
}

// ---------------------------------------------------------------------------
extern "C" void kernel_launch(void* const* d_in, const int* in_sizes, int n_in,
                              void* d_out, int out_size)
{
    const float* enc  = (const float*)d_in[0];  // [S,B,H]
    const float* lds  = (const float*)d_in[1];  // [2,1,B,H]
    const float* W    = (const float*)d_in[2];  // [H,H]
    const float* bias = (const float*)d_in[3];  // [H]
    float* out = (float*)d_out;                 // [1,1,S,B] == [S,B]

    energy_kernel<<<1024, 128>>>(lds, W);
    reduce_kernel<<<16, 256>>>(bias);
    score_kernel<<<(S_LEN / VPS) * B_SZ, 128>>>(enc, out);
    softmax_kernel<<<B_SZ, 1024>>>(out);
}

// round 11
// speedup vs baseline: 1.0535x; 1.0535x over previous
#include <cuda_runtime.h>
#include <cuda_bf16.h>

#define S_LEN 2048
#define B_SZ  16
#define H_DIM 1024

// 8 chunk-partial slabs (race-free -> no init kernel)
__device__ float    g_part[8][B_SZ * H_DIM];
__device__ float    g_scoresT[B_SZ * S_LEN];   // transposed scores [b][s]
__device__ unsigned g_max_u[B_SZ];             // ordered-uint max per column

// ordered-uint encoding of float (monotonic for atomicMax)
__device__ __forceinline__ unsigned f2ord(float f) {
    unsigned u = __float_as_uint(f);
    return (u & 0x80000000u) ? ~u : (u | 0x80000000u);
}
__device__ __forceinline__ float ord2f(unsigned x) {
    return (x & 0x80000000u) ? __uint_as_float(x & 0x7fffffffu)
                             : __uint_as_float(~x);
}

// ---------------------------------------------------------------------------
// Kernel 1 (R8-proven): energy partials. j in 8 chunks of 128 floats.
// Block = 128 thr (4 warps) covers (8 h-rows) x (one chunk); warp owns
// 2 rows x 16 b = 32 accumulators, each LDS.128 feeds 8 FFMAs. grid=1024.
// Block 0 also re-inits g_max_u (stream order protects the score kernel).
// ---------------------------------------------------------------------------
__global__ void __launch_bounds__(128)
energy_kernel(const float* __restrict__ lds,
              const float* __restrict__ W)
{
    __shared__ float4 s_st[16 * 32];     // [b][32 float4] (8KB)

    const int t    = threadIdx.x;
    const int warp = t >> 5;
    const int lane = t & 31;
    const int rg   = blockIdx.x >> 3;
    const int ch   = blockIdx.x & 7;
    const int row0 = rg * 8 + warp * 2;

    if (blockIdx.x == 0 && t < B_SZ)
        g_max_u[t] = 0u;                 // ordered encoding of -inf

    const float4* st4 = reinterpret_cast<const float4*>(lds);  // [B][256]
    const float4* W4  = reinterpret_cast<const float4*>(W);    // [H][256]

    #pragma unroll
    for (int i = 0; i < 4; ++i) {
        const int v = t + i * 128;
        const int b = v >> 5;
        const int k = v & 31;
        s_st[v] = st4[b * 256 + ch * 32 + k];
    }
    __syncthreads();

    const float4 w0 = W4[(size_t)row0 * 256 + ch * 32 + lane];
    const float4 w1 = W4[(size_t)(row0 + 1) * 256 + ch * 32 + lane];

    float a[32];                          // a[r*16+b]
    #pragma unroll
    for (int b = 0; b < 16; ++b) {
        const float4 s = s_st[b * 32 + lane];
        a[b]      = w0.x * s.x + w0.y * s.y + w0.z * s.z + w0.w * s.w;
        a[16 + b] = w1.x * s.x + w1.y * s.y + w1.z * s.z + w1.w * s.w;
    }

    // Value-halving butterfly: lane l ends holding warp-total of a[l].
    int n = 32;
    #pragma unroll
    for (int s = 16; s >= 1; s >>= 1) {
        const int  half = n >> 1;
        const bool up   = (lane & s) != 0;
        #pragma unroll
        for (int i = 0; i < half; ++i) {
            const float send = up ? a[i] : a[i + half];
            const float keep = up ? a[i + half] : a[i];
            a[i] = keep + __shfl_xor_sync(0xFFFFFFFF, send, s);
        }
        n = half;
    }

    const int r = lane >> 4;
    const int b = lane & 15;
    g_part[ch][(size_t)b * H_DIM + row0 + r] = a[0];
}

// ---------------------------------------------------------------------------
// Kernel 2: scores[s][b] = sum_h enc[s][b][h] * energy[b][h]
// energy row = bias + 8 partial slabs (L2-resident, rides free under the
// 128 MiB DRAM stream). Writes TRANSPOSED scores g_scoresT[b][s] and
// REDG-maxes each score into g_max_u[b] (hidden under the stream).
// ---------------------------------------------------------------------------
#define VPS 8
__global__ void __launch_bounds__(128, 8)
score_kernel(const float* __restrict__ enc,
             const float* __restrict__ bias)
{
    const int b  = blockIdx.x & (B_SZ - 1);
    const int s0 = (blockIdx.x >> 4) * VPS;
    const int t  = threadIdx.x;

    const float4* e4 = reinterpret_cast<const float4*>(enc);
    const float4* b4 = reinterpret_cast<const float4*>(bias);

    float4 g0 = b4[t];
    float4 g1 = b4[128 + t];
    #pragma unroll
    for (int c = 0; c < 8; ++c) {
        const float4* p4 = reinterpret_cast<const float4*>(g_part[c]);
        const float4 p0 = p4[b * (H_DIM / 4) + t];
        const float4 p1 = p4[b * (H_DIM / 4) + 128 + t];
        g0.x += p0.x; g0.y += p0.y; g0.z += p0.z; g0.w += p0.w;
        g1.x += p1.x; g1.y += p1.y; g1.z += p1.z; g1.w += p1.w;
    }

    float acc[VPS];
    #pragma unroll
    for (int i = 0; i < VPS; ++i) {
        const size_t row = ((size_t)(s0 + i) * B_SZ + b) * (H_DIM / 4);
        const float4 a0 = e4[row + t];
        const float4 a1 = e4[row + 128 + t];
        acc[i] = a0.x * g0.x + a0.y * g0.y + a0.z * g0.z + a0.w * g0.w
               + a1.x * g1.x + a1.y * g1.y + a1.z * g1.z + a1.w * g1.w;
    }

    #pragma unroll
    for (int i = 0; i < VPS; ++i)
        #pragma unroll
        for (int off = 16; off > 0; off >>= 1)
            acc[i] += __shfl_xor_sync(0xFFFFFFFF, acc[i], off);

    __shared__ float red[4][VPS];
    const int warp = t >> 5;
    const int lane = t & 31;
    if (lane == 0) {
        #pragma unroll
        for (int i = 0; i < VPS; ++i)
            red[warp][i] = acc[i];
    }
    __syncthreads();
    if (t < VPS) {
        const float v = red[0][t] + red[1][t] + red[2][t] + red[3][t];
        g_scoresT[(size_t)b * S_LEN + s0 + t] = v;
        atomicMax(&g_max_u[b], f2ord(v));
    }
}

// ---------------------------------------------------------------------------
// Kernel 3 v3: single-phase softmax. Max already in g_max_u[b].
// 16 blocks x 256 thr; coalesced float4 loads from g_scoresT (L2-hot),
// exp, ONE block-sum reduction, scattered stores to out[s][b].
// ---------------------------------------------------------------------------
__global__ void __launch_bounds__(256)
softmax_kernel(float* __restrict__ out)
{
    const int b = blockIdx.x;
    const int t = threadIdx.x;

    const float4* s4 = reinterpret_cast<const float4*>(g_scoresT + (size_t)b * S_LEN);
    float4 v0 = s4[t];
    float4 v1 = s4[t + 256];

    const float mx = ord2f(g_max_u[b]);

    v0.x = __expf(v0.x - mx); v0.y = __expf(v0.y - mx);
    v0.z = __expf(v0.z - mx); v0.w = __expf(v0.w - mx);
    v1.x = __expf(v1.x - mx); v1.y = __expf(v1.y - mx);
    v1.z = __expf(v1.z - mx); v1.w = __expf(v1.w - mx);

    float sum = v0.x + v0.y + v0.z + v0.w + v1.x + v1.y + v1.z + v1.w;

    __shared__ float sm[8];
    const int warp = t >> 5, lane = t & 31;
    #pragma unroll
    for (int off = 16; off > 0; off >>= 1)
        sum += __shfl_xor_sync(0xFFFFFFFF, sum, off);
    if (lane == 0) sm[warp] = sum;
    __syncthreads();
    if (warp == 0) {
        float s = (lane < 8) ? sm[lane] : 0.f;
        #pragma unroll
        for (int off = 4; off > 0; off >>= 1)
            s += __shfl_xor_sync(0xFFFFFFFF, s, off);
        if (lane == 0) sm[0] = s;
    }
    __syncthreads();
    const float inv = 1.0f / sm[0];

    const int sA = t * 4;            // v0 covers s = 4t..4t+3
    const int sB = 1024 + t * 4;     // v1 covers s = 1024+4t..
    out[(size_t)(sA + 0) * B_SZ + b] = v0.x * inv;
    out[(size_t)(sA + 1) * B_SZ + b] = v0.y * inv;
    out[(size_t)(sA + 2) * B_SZ + b] = v0.z * inv;
    out[(size_t)(sA + 3) * B_SZ + b] = v0.w * inv;
    out[(size_t)(sB + 0) * B_SZ + b] = v1.x * inv;
    out[(size_t)(sB + 1) * B_SZ + b] = v1.y * inv;
    out[(size_t)(sB + 2) * B_SZ + b] = v1.z * inv;
    out[(size_t)(sB + 3) * B_SZ + b] = v1.w * inv;
}

// ---------------------------------------------------------------------------
extern "C" void kernel_launch(void* const* d_in, const int* in_sizes, int n_in,
                              void* d_out, int out_size)
{
    const float* enc  = (const float*)d_in[0];  // [S,B,H]
    const float* lds  = (const float*)d_in[1];  // [2,1,B,H]
    const float* W    = (const float*)d_in[2];  // [H,H]
    const float* bias = (const float*)d_in[3];  // [H]
    float* out = (float*)d_out;                 // [1,1,S,B] == [S,B]

    energy_kernel<<<1024, 128>>>(lds, W);
    score_kernel<<<(S_LEN / VPS) * B_SZ, 128>>>(enc, bias);
    softmax_kernel<<<B_SZ, 256>>>(out);
}

// round 12
// speedup vs baseline: 1.0606x; 1.0067x over previous
#include <cuda_runtime.h>
#include <cuda_bf16.h>

#define S_LEN 2048
#define B_SZ  16
#define H_DIM 1024

// 8 chunk-partial slabs (race-free -> no init kernel)
__device__ float g_part[8][B_SZ * H_DIM];
__device__ float g_scoresT[B_SZ * S_LEN];   // transposed scores [b][s]

// ---------------------------------------------------------------------------
// Kernel 1: energy partials (R8 structure + W prefetch before sync).
// j in 8 chunks of 128 floats. Block = 128 thr (4 warps) covers (8 h-rows)
// x (one chunk); warp owns 2 rows x 16 b = 32 accumulators, each LDS.128
// feeds 8 FFMAs. W LDGs issued BEFORE staging+sync so DRAM latency overlaps.
// ---------------------------------------------------------------------------
__global__ void __launch_bounds__(128)
energy_kernel(const float* __restrict__ lds,
              const float* __restrict__ W)
{
    __shared__ float4 s_st[16 * 32];     // [b][32 float4] (8KB)

    const int t    = threadIdx.x;
    const int warp = t >> 5;
    const int lane = t & 31;
    const int rg   = blockIdx.x >> 3;
    const int ch   = blockIdx.x & 7;
    const int row0 = rg * 8 + warp * 2;

    const float4* st4 = reinterpret_cast<const float4*>(lds);  // [B][256]
    const float4* W4  = reinterpret_cast<const float4*>(W);    // [H][256]

    // Issue W loads FIRST — their ~600cyc DRAM latency overlaps staging+sync.
    const float4 w0 = W4[(size_t)row0 * 256 + ch * 32 + lane];
    const float4 w1 = W4[(size_t)(row0 + 1) * 256 + ch * 32 + lane];

    // Stage state half for this chunk: 512 float4, 4 per thread.
    #pragma unroll
    for (int i = 0; i < 4; ++i) {
        const int v = t + i * 128;
        const int b = v >> 5;
        const int k = v & 31;
        s_st[v] = st4[b * 256 + ch * 32 + k];
    }
    __syncthreads();

    float a[32];                          // a[r*16+b]
    #pragma unroll
    for (int b = 0; b < 16; ++b) {
        const float4 s = s_st[b * 32 + lane];
        a[b]      = w0.x * s.x + w0.y * s.y + w0.z * s.z + w0.w * s.w;
        a[16 + b] = w1.x * s.x + w1.y * s.y + w1.z * s.z + w1.w * s.w;
    }

    // Value-halving butterfly: lane l ends holding warp-total of a[l].
    int n = 32;
    #pragma unroll
    for (int s = 16; s >= 1; s >>= 1) {
        const int  half = n >> 1;
        const bool up   = (lane & s) != 0;
        #pragma unroll
        for (int i = 0; i < half; ++i) {
            const float send = up ? a[i] : a[i + half];
            const float keep = up ? a[i + half] : a[i];
            a[i] = keep + __shfl_xor_sync(0xFFFFFFFF, send, s);
        }
        n = half;
    }

    const int r = lane >> 4;
    const int b = lane & 15;
    g_part[ch][(size_t)b * H_DIM + row0 + r] = a[0];
}

// ---------------------------------------------------------------------------
// Kernel 2: scores[s][b] = sum_h enc[s][b][h] * energy[b][h]
// energy row = bias + 8 partial slabs (L2-resident, rides under the 128 MiB
// DRAM stream). Writes TRANSPOSED scores g_scoresT[b][s]. No atomics.
// ---------------------------------------------------------------------------
#define VPS 8
__global__ void __launch_bounds__(128, 8)
score_kernel(const float* __restrict__ enc,
             const float* __restrict__ bias)
{
    const int b  = blockIdx.x & (B_SZ - 1);
    const int s0 = (blockIdx.x >> 4) * VPS;
    const int t  = threadIdx.x;

    const float4* e4 = reinterpret_cast<const float4*>(enc);
    const float4* b4 = reinterpret_cast<const float4*>(bias);

    float4 g0 = b4[t];
    float4 g1 = b4[128 + t];
    #pragma unroll
    for (int c = 0; c < 8; ++c) {
        const float4* p4 = reinterpret_cast<const float4*>(g_part[c]);
        const float4 p0 = p4[b * (H_DIM / 4) + t];
        const float4 p1 = p4[b * (H_DIM / 4) + 128 + t];
        g0.x += p0.x; g0.y += p0.y; g0.z += p0.z; g0.w += p0.w;
        g1.x += p1.x; g1.y += p1.y; g1.z += p1.z; g1.w += p1.w;
    }

    float acc[VPS];
    #pragma unroll
    for (int i = 0; i < VPS; ++i) {
        const size_t row = ((size_t)(s0 + i) * B_SZ + b) * (H_DIM / 4);
        const float4 a0 = e4[row + t];
        const float4 a1 = e4[row + 128 + t];
        acc[i] = a0.x * g0.x + a0.y * g0.y + a0.z * g0.z + a0.w * g0.w
               + a1.x * g1.x + a1.y * g1.y + a1.z * g1.z + a1.w * g1.w;
    }

    #pragma unroll
    for (int i = 0; i < VPS; ++i)
        #pragma unroll
        for (int off = 16; off > 0; off >>= 1)
            acc[i] += __shfl_xor_sync(0xFFFFFFFF, acc[i], off);

    __shared__ float red[4][VPS];
    const int warp = t >> 5;
    const int lane = t & 31;
    if (lane == 0) {
        #pragma unroll
        for (int i = 0; i < VPS; ++i)
            red[warp][i] = acc[i];
    }
    __syncthreads();
    if (t < VPS)
        g_scoresT[(size_t)b * S_LEN + s0 + t] =
            red[0][t] + red[1][t] + red[2][t] + red[3][t];
}

// ---------------------------------------------------------------------------
// Kernel 3 v4: softmax with coalesced loads from g_scoresT.
// 16 blocks x 256 thr; 8 values/thread in registers, max-reduce then
// sum-reduce (both cheap now loads are float4), scattered stores to out.
// ---------------------------------------------------------------------------
__global__ void __launch_bounds__(256)
softmax_kernel(float* __restrict__ out)
{
    const int b = blockIdx.x;
    const int t = threadIdx.x;

    const float4* s4 = reinterpret_cast<const float4*>(g_scoresT + (size_t)b * S_LEN);
    float4 v0 = s4[t];
    float4 v1 = s4[t + 256];

    __shared__ float sm[8];
    const int warp = t >> 5, lane = t & 31;

    // ---- block max ----
    float mx = fmaxf(fmaxf(fmaxf(v0.x, v0.y), fmaxf(v0.z, v0.w)),
                     fmaxf(fmaxf(v1.x, v1.y), fmaxf(v1.z, v1.w)));
    #pragma unroll
    for (int off = 16; off > 0; off >>= 1)
        mx = fmaxf(mx, __shfl_xor_sync(0xFFFFFFFF, mx, off));
    if (lane == 0) sm[warp] = mx;
    __syncthreads();
    if (warp == 0) {
        float m = (lane < 8) ? sm[lane] : -3.402823466e38f;
        #pragma unroll
        for (int off = 4; off > 0; off >>= 1)
            m = fmaxf(m, __shfl_xor_sync(0xFFFFFFFF, m, off));
        if (lane == 0) sm[0] = m;
    }
    __syncthreads();
    mx = sm[0];
    __syncthreads();

    // ---- exp + block sum ----
    v0.x = __expf(v0.x - mx); v0.y = __expf(v0.y - mx);
    v0.z = __expf(v0.z - mx); v0.w = __expf(v0.w - mx);
    v1.x = __expf(v1.x - mx); v1.y = __expf(v1.y - mx);
    v1.z = __expf(v1.z - mx); v1.w = __expf(v1.w - mx);

    float sum = v0.x + v0.y + v0.z + v0.w + v1.x + v1.y + v1.z + v1.w;
    #pragma unroll
    for (int off = 16; off > 0; off >>= 1)
        sum += __shfl_xor_sync(0xFFFFFFFF, sum, off);
    if (lane == 0) sm[warp] = sum;
    __syncthreads();
    if (warp == 0) {
        float s = (lane < 8) ? sm[lane] : 0.f;
        #pragma unroll
        for (int off = 4; off > 0; off >>= 1)
            s += __shfl_xor_sync(0xFFFFFFFF, s, off);
        if (lane == 0) sm[0] = s;
    }
    __syncthreads();
    const float inv = 1.0f / sm[0];

    const int sA = t * 4;            // v0 covers s = 4t..4t+3
    const int sB = 1024 + t * 4;     // v1 covers s = 1024+4t..
    out[(size_t)(sA + 0) * B_SZ + b] = v0.x * inv;
    out[(size_t)(sA + 1) * B_SZ + b] = v0.y * inv;
    out[(size_t)(sA + 2) * B_SZ + b] = v0.z * inv;
    out[(size_t)(sA + 3) * B_SZ + b] = v0.w * inv;
    out[(size_t)(sB + 0) * B_SZ + b] = v1.x * inv;
    out[(size_t)(sB + 1) * B_SZ + b] = v1.y * inv;
    out[(size_t)(sB + 2) * B_SZ + b] = v1.z * inv;
    out[(size_t)(sB + 3) * B_SZ + b] = v1.w * inv;
}

// ---------------------------------------------------------------------------
extern "C" void kernel_launch(void* const* d_in, const int* in_sizes, int n_in,
                              void* d_out, int out_size)
{
    const float* enc  = (const float*)d_in[0];  // [S,B,H]
    const float* lds  = (const float*)d_in[1];  // [2,1,B,H]
    const float* W    = (const float*)d_in[2];  // [H,H]
    const float* bias = (const float*)d_in[3];  // [H]
    float* out = (float*)d_out;                 // [1,1,S,B] == [S,B]

    energy_kernel<<<1024, 128>>>(lds, W);
    score_kernel<<<(S_LEN / VPS) * B_SZ, 128>>>(enc, bias);
    softmax_kernel<<<B_SZ, 256>>>(out);
}